// round 14
// baseline (speedup 1.0000x reference)
#include <cuda_runtime.h>
#include <cuda_fp16.h>
#include <cuda.h>
#include <cstdint>

// ---------------------------------------------------------------------------
// SwitchFeedForward top-1 MoE FFN. T=8192, d_model=1024, d_ff=4096, E=8.
// Round 13: fused gemm1+gemm2 single launch (ticket queue + per-slot g_done
// counters; spin only on intra-grid state -> deadlock-free). Weight converts
// complete via graph event edge BEFORE gemm_fused (no flag spin on external
// kernels - round-12's starvation hazard removed).
// GEMM mainloop byte-identical to validated 547us / 4.15e-4 version.
// ---------------------------------------------------------------------------

#define T_TOK   8192
#define DM      1024
#define DF      4096
#define NE      8

#define OFF_CNT   (T_TOK * DM)
#define OFF_PSUM  (OFF_CNT + NE)
#define OFF_ZERO  (OFF_PSUM + NE)
#define OFF_PMAX  (OFF_ZERO + 1)

#define BM 128
#define BN 128
#define BKE 32                 // k elems per block (64 bytes per row, SW64)
#define MAX_SLOTS 80

#define NT1 2272               // 71 slots * 32 x-blocks (gemm1 tiles)
#define NT2 568                // 71 slots * 8  x-blocks (gemm2 tiles)
#define NT_TOTAL (NT1 + NT2)   // 2840

#define A_BYTES   8192         // 128 rows * 64B
#define B_BYTES   8192         // 128 rows * 64B
#define STG       16384        // A + B
#define STAGES    6
#define BAR_OFF   (STAGES * STG)          // 98304
#define TICK_OFF  (BAR_OFF + 112)
#define TOKS_OFF  (BAR_OFF + 128)
#define SMEM_TOTAL (TOKS_OFF + 512)       // 98944 -> 2 CTAs/SM

// ----------------------------- device scratch ------------------------------
__device__ __half g_Xh[(size_t)T_TOK * DM];
__device__ __half g_w1h[(size_t)NE * DF * DM];
__device__ __half g_w2h[(size_t)NE * DM * DF];
__device__ __half g_Hh[(size_t)T_TOK * DF];

__device__ float g_probs[T_TOK * NE];
__device__ int   g_routes[T_TOK];
__device__ int   g_cnt[NE];
__device__ int   g_off[NE];
__device__ int   g_fill[NE];
__device__ int   g_perm[T_TOK];
__device__ int   g_slot_e[MAX_SLOTS];
__device__ int   g_slot_row0[MAX_SLOTS];
__device__ int   g_slot_nv[MAX_SLOTS];
__device__ int   g_nslots;

__device__ int   g_ticket;
__device__ int   g_done[MAX_SLOTS];

// ----------------------------- PTX helpers ---------------------------------
__device__ __forceinline__ uint32_t s2u(const void* p) {
    uint32_t a;
    asm("{ .reg .u64 t; cvta.to.shared.u64 t, %1; cvt.u32.u64 %0, t; }" : "=r"(a) : "l"(p));
    return a;
}

__device__ __forceinline__ int ld_acq(const int* p) {
    int v;
    asm volatile("ld.acquire.gpu.global.b32 %0, [%1];" : "=r"(v) : "l"(p) : "memory");
    return v;
}

#define MBAR_INIT(a, c) \
    asm volatile("mbarrier.init.shared.b64 [%0], %1;" :: "r"(a), "r"(c) : "memory")
#define MBAR_EXPECT(a, b) \
    asm volatile("mbarrier.arrive.expect_tx.shared.b64 _, [%0], %1;" :: "r"(a), "r"(b) : "memory")
#define MBAR_ARRIVE(a) \
    asm volatile("mbarrier.arrive.shared.b64 _, [%0];" :: "r"(a) : "memory")

__device__ __forceinline__ void mbar_wait(uint32_t a, uint32_t par) {
    asm volatile(
        "{\n\t.reg .pred P;\n\t"
        "WL%=:\n\t"
        "mbarrier.try_wait.parity.acquire.cta.shared::cta.b64 P, [%0], %1, 0x989680;\n\t"
        "@P bra WD%=;\n\t"
        "bra WL%=;\n\t"
        "WD%=:\n\t}"
        :: "r"(a), "r"(par) : "memory");
}

__device__ __forceinline__ void tma2d(uint32_t dst, const CUtensorMap* m, int cx, int cy, uint32_t mbar) {
    asm volatile(
        "cp.async.bulk.tensor.2d.shared::cta.global.tile.mbarrier::complete_tx::bytes "
        "[%0], [%1, {%2, %3}], [%4];"
        :: "r"(dst), "l"(m), "r"(cx), "r"(cy), "r"(mbar) : "memory");
}

#define LDSM_X4(r0, r1, r2, r3, addr) \
    asm volatile("ldmatrix.sync.aligned.m8n8.x4.shared.b16 {%0,%1,%2,%3}, [%4];" \
        : "=r"(r0), "=r"(r1), "=r"(r2), "=r"(r3) : "r"(addr))

#define MMA16816(d, a, b0v, b1v) \
    asm volatile("mma.sync.aligned.m16n8k16.row.col.f32.f16.f16.f32 " \
        "{%0,%1,%2,%3}, {%4,%5,%6,%7}, {%8,%9}, {%0,%1,%2,%3};" \
        : "+f"((d)[0]), "+f"((d)[1]), "+f"((d)[2]), "+f"((d)[3]) \
        : "r"((a)[0]), "r"((a)[1]), "r"((a)[2]), "r"((a)[3]), "r"(b0v), "r"(b1v))

// ----------------------------- small kernels -------------------------------
__global__ void init_kernel() {
    int t = threadIdx.x;
    if (t < NE) g_cnt[t] = 0;
    if (t == 0) g_ticket = 0;
    if (t < MAX_SLOTS) g_done[t] = 0;
}

// One warp per token, float4-vectorized.
__global__ void router_kernel(const float* __restrict__ x,
                              const float* __restrict__ sw,
                              const float* __restrict__ sb,
                              float* __restrict__ out_pmax) {
    int warp = threadIdx.x >> 5;
    int lane = threadIdx.x & 31;
    int t = blockIdx.x * 8 + warp;
    if (t >= T_TOK) return;

    const float4* xp = (const float4*)(x + (size_t)t * DM);
    float acc[NE];
#pragma unroll
    for (int e = 0; e < NE; e++) acc[e] = 0.f;
#pragma unroll
    for (int j = 0; j < DM / 128; j++) {
        int idx = lane + 32 * j;
        float4 xv = xp[idx];
#pragma unroll
        for (int e = 0; e < NE; e++) {
            float4 wv = ((const float4*)(sw + e * DM))[idx];
            acc[e] += xv.x * wv.x + xv.y * wv.y + xv.z * wv.z + xv.w * wv.w;
        }
    }
#pragma unroll
    for (int o = 16; o > 0; o >>= 1)
#pragma unroll
        for (int e = 0; e < NE; e++)
            acc[e] += __shfl_xor_sync(0xffffffffu, acc[e], o);

    if (lane == 0) {
        float l[NE], m = -1e30f;
#pragma unroll
        for (int e = 0; e < NE; e++) { l[e] = acc[e] + sb[e]; m = fmaxf(m, l[e]); }
        float p[NE], s = 0.f;
#pragma unroll
        for (int e = 0; e < NE; e++) { p[e] = expf(l[e] - m); s += p[e]; }
        float inv = 1.f / s;
        int best = 0; float bp = p[0];
#pragma unroll
        for (int e = 1; e < NE; e++) if (p[e] > bp) { bp = p[e]; best = e; }
#pragma unroll
        for (int e = 0; e < NE; e++) g_probs[t * NE + e] = p[e] * inv;
        out_pmax[t] = bp * inv;
        g_routes[t] = best;
        atomicAdd(&g_cnt[best], 1);
    }
}

__global__ void finalize_kernel(float* __restrict__ out) {
    int tid = threadIdx.x, warp = tid >> 5, lane = tid & 31;
    if (warp < NE) {
        float sum = 0.f;
        for (int t = lane; t < T_TOK; t += 32) sum += g_probs[t * NE + warp];
#pragma unroll
        for (int o = 16; o > 0; o >>= 1) sum += __shfl_xor_sync(0xffffffffu, sum, o);
        if (lane == 0) out[OFF_PSUM + warp] = sum;
    }
    if (tid == 0) {
        int off = 0, ns = 0;
        for (int e = 0; e < NE; e++) {
            int c = g_cnt[e];
            g_off[e] = off; g_fill[e] = 0;
            out[OFF_CNT + e] = (float)c;
            for (int i = 0; i < c; i += BM) {
                g_slot_e[ns] = e; g_slot_row0[ns] = off + i;
                g_slot_nv[ns] = min(BM, c - i); ns++;
            }
            off += c;
        }
        g_nslots = ns;
        out[OFF_ZERO] = 0.f;
    }
}

__global__ void scatter_kernel() {
    int t = blockIdx.x * blockDim.x + threadIdx.x;
    if (t < T_TOK) {
        int e = g_routes[t];
        int pos = g_off[e] + atomicAdd(&g_fill[e], 1);
        g_perm[pos] = t;
    }
}

__global__ void convert_cast_kernel(const float4* __restrict__ src,
                                    uint2* __restrict__ dst, int n4) {
    int i = blockIdx.x * blockDim.x + threadIdx.x;
    if (i >= n4) return;
    float4 v = src[i];
    __half2 p0 = __floats2half2_rn(v.x, v.y);
    __half2 p1 = __floats2half2_rn(v.z, v.w);
    dst[i] = make_uint2(*(uint32_t*)&p0, *(uint32_t*)&p1);
}

__global__ void gather_x_kernel(const float* __restrict__ x) {
    int r = blockIdx.x;
    int t = threadIdx.x;
    int tok = g_perm[r];
    float4 v = ((const float4*)(x + (size_t)tok * DM))[t];
    __half2 p0 = __floats2half2_rn(v.x, v.y);
    __half2 p1 = __floats2half2_rn(v.z, v.w);
    ((uint2*)g_Xh)[(size_t)r * (DM / 4) + t] = make_uint2(*(uint32_t*)&p0, *(uint32_t*)&p1);
}

// ----------------------------- GEMM building blocks ------------------------
__device__ __forceinline__ void produce_all(
    uint32_t sb,
    const CUtensorMap* mA, const CUtensorMap* mB,
    int rowA, int rowB, int nkb)
{
    uint32_t FULL = sb + BAR_OFF, EMPTY = sb + BAR_OFF + 64;
    for (int L = 0; L < nkb; L++) {
        int s = L % STAGES;
        if (L >= STAGES) mbar_wait(EMPTY + 8 * s, ((L / STAGES) - 1) & 1);
        uint32_t stg = sb + s * STG;
        uint32_t fb = FULL + 8 * s;
        MBAR_EXPECT(fb, STG);
        tma2d(stg,           mA, L * BKE, rowA, fb);
        tma2d(stg + A_BYTES, mB, L * BKE, rowB, fb);
    }
}

__device__ __forceinline__ void consume_all(
    uint32_t sb, int nkb, int lane, int mw, int nw,
    float (&acc)[4][8][4])
{
    int arow_l = (lane & 7) + ((lane >> 3) & 1) * 8;
    uint32_t acolsel = (uint32_t)((lane >> 4) * 16);
    uint32_t apat = (uint32_t)(((arow_l >> 1) & 3) << 4);
    uint32_t aoff[4];
#pragma unroll
    for (int i = 0; i < 4; i++) aoff[i] = (uint32_t)((mw * 64 + i * 16 + arow_l) * 64);

    int brow_l = ((lane >> 4) & 1) * 8 + (lane & 7);
    uint32_t bcolsel = (uint32_t)(((lane >> 3) & 1) * 16);
    uint32_t bpat = (uint32_t)(((brow_l >> 1) & 3) << 4);
    uint32_t boff[4];
#pragma unroll
    for (int jp = 0; jp < 4; jp++) boff[jp] = (uint32_t)((nw * 64 + jp * 16 + brow_l) * 64);

    uint32_t FULL = sb + BAR_OFF, EMPTY = sb + BAR_OFF + 64;

    for (int kb = 0; kb < nkb; kb++) {
        int s = kb % STAGES;
        mbar_wait(FULL + 8 * s, (kb / STAGES) & 1);
        uint32_t stg = sb + s * STG;
#pragma unroll
        for (int st = 0; st < 2; st++) {
            uint32_t kbyte = (uint32_t)(st * 32);
            uint32_t axor = (kbyte + acolsel) ^ apat;
            uint32_t bxor = (kbyte + bcolsel) ^ bpat;
            uint32_t ah[4][4];
#pragma unroll
            for (int i = 0; i < 4; i++) {
                uint32_t ad = stg + aoff[i] + axor;
                LDSM_X4(ah[i][0], ah[i][1], ah[i][2], ah[i][3], ad);
            }
            uint32_t bh[2][4];
            {
                uint32_t bd0 = stg + A_BYTES + boff[0] + bxor;
                LDSM_X4(bh[0][0], bh[0][1], bh[0][2], bh[0][3], bd0);
            }
#pragma unroll
            for (int jp = 0; jp < 4; jp++) {
                int cur = jp & 1;
                int nxt = cur ^ 1;
                if (jp < 3) {
                    uint32_t bdn = stg + A_BYTES + boff[jp + 1] + bxor;
                    LDSM_X4(bh[nxt][0], bh[nxt][1], bh[nxt][2], bh[nxt][3], bdn);
                }
#pragma unroll
                for (int i = 0; i < 4; i++) {
                    MMA16816(acc[i][2 * jp],     ah[i], bh[cur][0], bh[cur][1]);
                    MMA16816(acc[i][2 * jp + 1], ah[i], bh[cur][2], bh[cur][3]);
                }
            }
        }
        if (lane == 0) MBAR_ARRIVE(EMPTY + 8 * s);
    }
}

// ----------------------------- fused GEMM kernel ---------------------------
// Ticket [0, NT1): gemm1 tile (slot = t/32, xb = t%32), nkb=32, A=Xh, B=w1.
// Ticket [NT1, NT_TOTAL): gemm2 tile (slot = u/8, xb = u%8), nkb=128, A=Hh,
// B=w2; producer spins until all 32 gemm1 tiles of its slot completed.
// Deadlock-free: gemm2 tickets only exist once all gemm1 tickets are held by
// resident-or-done CTAs of this same grid, which progress independently.
__global__ __launch_bounds__(160, 2)
void gemm_fused(const __grid_constant__ CUtensorMap mX,
                const __grid_constant__ CUtensorMap mW1,
                const __grid_constant__ CUtensorMap mH,
                const __grid_constant__ CUtensorMap mW2,
                const float* __restrict__ b1,
                const float* __restrict__ b2,
                float* __restrict__ out)
{
    extern __shared__ __align__(1024) uint8_t smem_buf[];
    uint32_t sb = s2u(smem_buf);
    int tid = threadIdx.x, lane = tid & 31, warp = tid >> 5;
    int* toks = (int*)(smem_buf + TOKS_OFF);
    int* tick = (int*)(smem_buf + TICK_OFF);

    if (tid == 0) {
        *tick = atomicAdd(&g_ticket, 1);
        for (int s = 0; s < STAGES; s++) {
            MBAR_INIT(sb + BAR_OFF + 8 * s, 1);
            MBAR_INIT(sb + BAR_OFF + 64 + 8 * s, 4);
        }
    }
    asm volatile("fence.proxy.async.shared::cta;" ::: "memory");
    __syncthreads();

    int ticket = *tick;
    bool is1 = ticket < NT1;
    int slot, xb;
    if (is1) { slot = ticket >> 5; xb = ticket & 31; }
    else     { int u = ticket - NT1; slot = u >> 3; xb = u & 7; }
    if (slot >= g_nslots) return;   // uniform across CTA

    int e = g_slot_e[slot], row0 = g_slot_row0[slot], nv = g_slot_nv[slot];
    int nb = xb * BN;

    if (!is1 && tid < BM) toks[tid] = g_perm[row0 + min(tid, nv - 1)];
    __syncthreads();   // all 5 warps still present

    if (warp == 4) {
        if (lane == 0) {
            if (is1) {
                produce_all(sb, &mX, &mW1, row0, e * DF + nb, DM / BKE);
            } else {
                while (ld_acq(&g_done[slot]) < 32) __nanosleep(128);
                produce_all(sb, &mH, &mW2, row0, e * DM + nb, DF / BKE);
            }
        }
        return;
    }

    float acc[4][8][4];
#pragma unroll
    for (int i = 0; i < 4; i++)
#pragma unroll
        for (int j = 0; j < 8; j++)
#pragma unroll
            for (int q = 0; q < 4; q++) acc[i][j][q] = 0.f;

    int mw = warp & 1, nw = warp >> 1;
    consume_all(sb, is1 ? (DM / BKE) : (DF / BKE), lane, mw, nw, acc);

    int rb = mw * 64 + (lane >> 2);
    int cbase = nb + nw * 64 + 2 * (lane & 3);

    if (is1) {
        const float* bb = b1 + (size_t)e * DF;
#pragma unroll
        for (int i = 0; i < 4; i++) {
#pragma unroll
            for (int half = 0; half < 2; half++) {
                int r = rb + i * 16 + half * 8;
                if (r < nv) {
                    size_t rowg = (size_t)(row0 + r);
#pragma unroll
                    for (int j = 0; j < 8; j++) {
                        int colg = cbase + j * 8;
                        float2 bv = *(const float2*)(bb + colg);
                        float v0 = fmaxf(acc[i][j][2 * half]     + bv.x, 0.f);
                        float v1 = fmaxf(acc[i][j][2 * half + 1] + bv.y, 0.f);
                        __half2 hp = __floats2half2_rn(v0, v1);
                        *(uint32_t*)(g_Hh + rowg * DF + colg) = *(uint32_t*)&hp;
                    }
                }
            }
        }
        // signal completion of this gemm1 tile (4 consumer warps = 128 thr)
        asm volatile("bar.sync 1, 128;" ::: "memory");
        if (tid == 0) {
            __threadfence();
            atomicAdd(&g_done[slot], 1);
        }
    } else {
        const float* bb = b2 + (size_t)e * DM;
#pragma unroll
        for (int i = 0; i < 4; i++) {
#pragma unroll
            for (int half = 0; half < 2; half++) {
                int r = rb + i * 16 + half * 8;
                if (r < nv) {
                    int tok = toks[r];
                    float* op = out + (size_t)tok * DM;
#pragma unroll
                    for (int j = 0; j < 8; j++) {
                        int colg = cbase + j * 8;
                        float2 bv = *(const float2*)(bb + colg);
                        float2 v;
                        v.x = acc[i][j][2 * half]     + bv.x;
                        v.y = acc[i][j][2 * half + 1] + bv.y;
                        *(float2*)(op + colg) = v;
                    }
                }
            }
        }
    }
}

// ------------------------------- host side ---------------------------------
typedef CUresult (CUDAAPI *PFN_encodeTiled)(
    CUtensorMap*, CUtensorMapDataType, cuuint32_t, void*,
    const cuuint64_t*, const cuuint64_t*, const cuuint32_t*, const cuuint32_t*,
    CUtensorMapInterleave, CUtensorMapSwizzle, CUtensorMapL2promotion, CUtensorMapFloatOOBfill);

static PFN_encodeTiled get_encode_fn() {
    static PFN_encodeTiled fn = nullptr;
    if (!fn) {
        void* p = nullptr;
        cudaDriverEntryPointQueryResult st;
#if CUDART_VERSION >= 12050
        cudaGetDriverEntryPointByVersion("cuTensorMapEncodeTiled", &p, 12000, cudaEnableDefault, &st);
#else
        cudaGetDriverEntryPoint("cuTensorMapEncodeTiled", &p, cudaEnableDefault, &st);
#endif
        fn = (PFN_encodeTiled)p;
    }
    return fn;
}

static void make_map_2d(CUtensorMap* m, void* ptr, uint64_t d0, uint64_t d1, uint32_t box_rows) {
    cuuint64_t gd[2] = {d0, d1};
    cuuint64_t gs[1] = {d0 * 2};
    cuuint32_t box[2] = {BKE, box_rows};
    cuuint32_t es[2] = {1, 1};
    get_encode_fn()(m, CU_TENSOR_MAP_DATA_TYPE_FLOAT16, 2, ptr, gd, gs, box, es,
                    CU_TENSOR_MAP_INTERLEAVE_NONE, CU_TENSOR_MAP_SWIZZLE_64B,
                    CU_TENSOR_MAP_L2_PROMOTION_L2_128B, CU_TENSOR_MAP_FLOAT_OOB_FILL_NONE);
}

extern "C" void kernel_launch(void* const* d_in, const int* in_sizes, int n_in,
                              void* d_out, int out_size) {
    const float* x  = (const float*)d_in[0];
    const float* sw = (const float*)d_in[1];
    const float* sb = (const float*)d_in[2];
    const float* w1 = (const float*)d_in[3];
    const float* b1 = (const float*)d_in[4];
    const float* w2 = (const float*)d_in[5];
    const float* b2 = (const float*)d_in[6];
    float* out = (float*)d_out;

    static cudaStream_t s_conv = nullptr;
    static cudaEvent_t ev_root = nullptr, ev_conv = nullptr;
    if (!s_conv) {
        cudaStreamCreateWithFlags(&s_conv, cudaStreamNonBlocking);
        cudaEventCreateWithFlags(&ev_root, cudaEventDisableTiming);
        cudaEventCreateWithFlags(&ev_conv, cudaEventDisableTiming);
    }

    void *p_xh, *p_w1h, *p_w2h, *p_hh;
    cudaGetSymbolAddress(&p_xh, g_Xh);
    cudaGetSymbolAddress(&p_w1h, g_w1h);
    cudaGetSymbolAddress(&p_w2h, g_w2h);
    cudaGetSymbolAddress(&p_hh, g_Hh);

    CUtensorMap mXh, mW1h, mW2h, mHh;
    make_map_2d(&mXh,  p_xh,  DM, T_TOK, 128);
    make_map_2d(&mW1h, p_w1h, DM, (uint64_t)NE * DF, 128);
    make_map_2d(&mW2h, p_w2h, DF, (uint64_t)NE * DM, 128);
    make_map_2d(&mHh,  p_hh,  DF, T_TOK, 128);

    cudaFuncSetAttribute(gemm_fused, cudaFuncAttributeMaxDynamicSharedMemorySize, SMEM_TOTAL);

    const int n4 = NE * DF * DM / 4;

    // fork: converts overlap the routing chain on a side stream
    cudaEventRecord(ev_root, 0);
    cudaStreamWaitEvent(s_conv, ev_root, 0);
    convert_cast_kernel<<<n4 / 256, 256, 0, s_conv>>>((const float4*)w1, (uint2*)p_w1h, n4);
    convert_cast_kernel<<<n4 / 256, 256, 0, s_conv>>>((const float4*)w2, (uint2*)p_w2h, n4);
    cudaEventRecord(ev_conv, s_conv);

    // main chain
    init_kernel<<<1, 128>>>();
    router_kernel<<<T_TOK / 8, 256>>>(x, sw, sb, out + OFF_PMAX);
    finalize_kernel<<<1, 256>>>(out);
    scatter_kernel<<<T_TOK / 256, 256>>>();
    gather_x_kernel<<<T_TOK, 256>>>(x);

    // graph edge: both converts complete before the fused GEMM grid launches
    cudaStreamWaitEvent(0, ev_conv, 0);
    gemm_fused<<<NT_TOTAL, 160, SMEM_TOTAL>>>(mXh, mW1h, mHh, mW2h, b1, b2, out);
}

// round 16
// speedup vs baseline: 1.0750x; 1.0750x over previous
#include <cuda_runtime.h>
#include <cuda_fp16.h>
#include <cuda.h>
#include <cstdint>

// ---------------------------------------------------------------------------
// SwitchFeedForward top-1 MoE FFN. T=8192, d_model=1024, d_ff=4096, E=8.
// Round 15: byte-identical resubmit of round-14 (infra failed twice; design
// untested). Round-10 base (best: 546.7us / 4.15e-4) with two overhead cuts:
//   (1) BKE 32->64, SW64->SW128, STAGES 6->3: same smem footprint, half the
//       mbarrier waits / TMA requests per GEMM (bitwise-identical K order).
//   (2) scatter+gather fused into one warp-per-token kernel.
// GEMM math and HMMA schedule unchanged.
// ---------------------------------------------------------------------------

#define T_TOK   8192
#define DM      1024
#define DF      4096
#define NE      8

#define OFF_CNT   (T_TOK * DM)
#define OFF_PSUM  (OFF_CNT + NE)
#define OFF_ZERO  (OFF_PSUM + NE)
#define OFF_PMAX  (OFF_ZERO + 1)

#define BM 128
#define BN 128
#define BKE 64                 // k elems per block (128 bytes per row, SW128)
#define MAX_SLOTS 80

#define A_BYTES   16384        // 128 rows * 128B
#define B_BYTES   16384        // 128 rows * 128B
#define STG       32768        // A + B
#define STAGES    3
#define BAR_OFF   (STAGES * STG)          // 98304 (same as round 10)
#define TOKS_OFF  (BAR_OFF + 128)
#define SMEM_TOTAL (TOKS_OFF + 512)       // 98944 -> 2 CTAs/SM

// ----------------------------- device scratch ------------------------------
__device__ __half g_Xh[(size_t)T_TOK * DM];
__device__ __half g_w1h[(size_t)NE * DF * DM];
__device__ __half g_w2h[(size_t)NE * DM * DF];
__device__ __half g_Hh[(size_t)T_TOK * DF];

__device__ float g_probs[T_TOK * NE];
__device__ int   g_routes[T_TOK];
__device__ int   g_cnt[NE];
__device__ int   g_off[NE];
__device__ int   g_fill[NE];
__device__ int   g_perm[T_TOK];
__device__ int   g_slot_e[MAX_SLOTS];
__device__ int   g_slot_row0[MAX_SLOTS];
__device__ int   g_slot_nv[MAX_SLOTS];
__device__ int   g_nslots;

// ----------------------------- PTX helpers ---------------------------------
__device__ __forceinline__ uint32_t s2u(const void* p) {
    uint32_t a;
    asm("{ .reg .u64 t; cvta.to.shared.u64 t, %1; cvt.u32.u64 %0, t; }" : "=r"(a) : "l"(p));
    return a;
}

#define MBAR_INIT(a, c) \
    asm volatile("mbarrier.init.shared.b64 [%0], %1;" :: "r"(a), "r"(c) : "memory")
#define MBAR_EXPECT(a, b) \
    asm volatile("mbarrier.arrive.expect_tx.shared.b64 _, [%0], %1;" :: "r"(a), "r"(b) : "memory")
#define MBAR_ARRIVE(a) \
    asm volatile("mbarrier.arrive.shared.b64 _, [%0];" :: "r"(a) : "memory")

__device__ __forceinline__ void mbar_wait(uint32_t a, uint32_t par) {
    asm volatile(
        "{\n\t.reg .pred P;\n\t"
        "WL%=:\n\t"
        "mbarrier.try_wait.parity.acquire.cta.shared::cta.b64 P, [%0], %1, 0x989680;\n\t"
        "@P bra WD%=;\n\t"
        "bra WL%=;\n\t"
        "WD%=:\n\t}"
        :: "r"(a), "r"(par) : "memory");
}

__device__ __forceinline__ void tma2d(uint32_t dst, const CUtensorMap* m, int cx, int cy, uint32_t mbar) {
    asm volatile(
        "cp.async.bulk.tensor.2d.shared::cta.global.tile.mbarrier::complete_tx::bytes "
        "[%0], [%1, {%2, %3}], [%4];"
        :: "r"(dst), "l"(m), "r"(cx), "r"(cy), "r"(mbar) : "memory");
}

#define LDSM_X4(r0, r1, r2, r3, addr) \
    asm volatile("ldmatrix.sync.aligned.m8n8.x4.shared.b16 {%0,%1,%2,%3}, [%4];" \
        : "=r"(r0), "=r"(r1), "=r"(r2), "=r"(r3) : "r"(addr))

#define MMA16816(d, a, b0v, b1v) \
    asm volatile("mma.sync.aligned.m16n8k16.row.col.f32.f16.f16.f32 " \
        "{%0,%1,%2,%3}, {%4,%5,%6,%7}, {%8,%9}, {%0,%1,%2,%3};" \
        : "+f"((d)[0]), "+f"((d)[1]), "+f"((d)[2]), "+f"((d)[3]) \
        : "r"((a)[0]), "r"((a)[1]), "r"((a)[2]), "r"((a)[3]), "r"(b0v), "r"(b1v))

// ----------------------------- small kernels -------------------------------
__global__ void init_kernel() {
    if (threadIdx.x < NE) g_cnt[threadIdx.x] = 0;
}

// One warp per token, float4-vectorized (round-10 validated numerics).
__global__ void router_kernel(const float* __restrict__ x,
                              const float* __restrict__ sw,
                              const float* __restrict__ sb,
                              float* __restrict__ out_pmax) {
    int warp = threadIdx.x >> 5;
    int lane = threadIdx.x & 31;
    int t = blockIdx.x * 8 + warp;
    if (t >= T_TOK) return;

    const float4* xp = (const float4*)(x + (size_t)t * DM);
    float acc[NE];
#pragma unroll
    for (int e = 0; e < NE; e++) acc[e] = 0.f;
#pragma unroll
    for (int j = 0; j < DM / 128; j++) {
        int idx = lane + 32 * j;
        float4 xv = xp[idx];
#pragma unroll
        for (int e = 0; e < NE; e++) {
            float4 wv = ((const float4*)(sw + e * DM))[idx];
            acc[e] += xv.x * wv.x + xv.y * wv.y + xv.z * wv.z + xv.w * wv.w;
        }
    }
#pragma unroll
    for (int o = 16; o > 0; o >>= 1)
#pragma unroll
        for (int e = 0; e < NE; e++)
            acc[e] += __shfl_xor_sync(0xffffffffu, acc[e], o);

    if (lane == 0) {
        float l[NE], m = -1e30f;
#pragma unroll
        for (int e = 0; e < NE; e++) { l[e] = acc[e] + sb[e]; m = fmaxf(m, l[e]); }
        float p[NE], s = 0.f;
#pragma unroll
        for (int e = 0; e < NE; e++) { p[e] = expf(l[e] - m); s += p[e]; }
        float inv = 1.f / s;
        int best = 0; float bp = p[0];
#pragma unroll
        for (int e = 1; e < NE; e++) if (p[e] > bp) { bp = p[e]; best = e; }
#pragma unroll
        for (int e = 0; e < NE; e++) g_probs[t * NE + e] = p[e] * inv;
        out_pmax[t] = bp * inv;
        g_routes[t] = best;
        atomicAdd(&g_cnt[best], 1);
    }
}

__global__ void finalize_kernel(float* __restrict__ out) {
    int tid = threadIdx.x, warp = tid >> 5, lane = tid & 31;
    if (warp < NE) {
        float sum = 0.f;
        for (int t = lane; t < T_TOK; t += 32) sum += g_probs[t * NE + warp];
#pragma unroll
        for (int o = 16; o > 0; o >>= 1) sum += __shfl_xor_sync(0xffffffffu, sum, o);
        if (lane == 0) out[OFF_PSUM + warp] = sum;
    }
    if (tid == 0) {
        int off = 0, ns = 0;
        for (int e = 0; e < NE; e++) {
            int c = g_cnt[e];
            g_off[e] = off; g_fill[e] = 0;
            out[OFF_CNT + e] = (float)c;
            for (int i = 0; i < c; i += BM) {
                g_slot_e[ns] = e; g_slot_row0[ns] = off + i;
                g_slot_nv[ns] = min(BM, c - i); ns++;
            }
            off += c;
        }
        g_nslots = ns;
        out[OFF_ZERO] = 0.f;
    }
}

// Fused scatter + gather: one warp per token. Lane 0 claims the slot,
// the warp converts/copies the fp32 row into g_Xh[pos] as fp16.
__global__ void scatter_gather_kernel(const float* __restrict__ x) {
    int warp = threadIdx.x >> 5;
    int lane = threadIdx.x & 31;
    int t = blockIdx.x * 8 + warp;
    if (t >= T_TOK) return;

    int pos = 0;
    if (lane == 0) {
        int e = g_routes[t];
        pos = g_off[e] + atomicAdd(&g_fill[e], 1);
        g_perm[pos] = t;
    }
    pos = __shfl_sync(0xffffffffu, pos, 0);

    const float4* src = (const float4*)(x + (size_t)t * DM);
    uint2* dst = (uint2*)g_Xh + (size_t)pos * (DM / 4);
#pragma unroll
    for (int q = 0; q < 8; q++) {
        float4 v = src[lane + 32 * q];
        __half2 p0 = __floats2half2_rn(v.x, v.y);
        __half2 p1 = __floats2half2_rn(v.z, v.w);
        dst[lane + 32 * q] = make_uint2(*(uint32_t*)&p0, *(uint32_t*)&p1);
    }
}

__global__ void convert_cast_kernel(const float4* __restrict__ src,
                                    uint2* __restrict__ dst, int n4) {
    int i = blockIdx.x * blockDim.x + threadIdx.x;
    if (i >= n4) return;
    float4 v = src[i];
    __half2 p0 = __floats2half2_rn(v.x, v.y);
    __half2 p1 = __floats2half2_rn(v.z, v.w);
    dst[i] = make_uint2(*(uint32_t*)&p0, *(uint32_t*)&p1);
}

// ----------------------------- GEMM building blocks ------------------------
// Producer: one thread streams all k-blocks through the 3-stage ring.
__device__ __forceinline__ void produce_all(
    uint32_t sb,
    const CUtensorMap* mA, const CUtensorMap* mB,
    int rowA, int rowB, int nkb)
{
    uint32_t FULL = sb + BAR_OFF, EMPTY = sb + BAR_OFF + 64;
    for (int L = 0; L < nkb; L++) {
        int s = L % STAGES;
        if (L >= STAGES) mbar_wait(EMPTY + 8 * s, ((L / STAGES) - 1) & 1);
        uint32_t stg = sb + s * STG;
        uint32_t fb = FULL + 8 * s;
        MBAR_EXPECT(fb, STG);
        tma2d(stg,           mA, L * BKE, rowA, fb);
        tma2d(stg + A_BYTES, mB, L * BKE, rowB, fb);
    }
}

// Consumer: 4 warps, warp tile 64x64 (mw in {0,1}, nw in {0,1}).
// SW128 swizzle: 128B rows; byte c in row -> c ^ ((row & 7) << 4).
// Warp-tile row offsets are 0 mod 8, so the xor pattern is (lane&7)<<4.
// K order inside a k-block: st=0..3 covering bytes 0..127 sequentially --
// identical accumulation order to the old BKE=32 pipeline (bitwise equal).
__device__ __forceinline__ void consume_all(
    uint32_t sb, int nkb, int lane, int mw, int nw,
    float (&acc)[4][8][4])
{
    int arow_l = (lane & 7) + ((lane >> 3) & 1) * 8;
    uint32_t acolsel = (uint32_t)((lane >> 4) * 16);
    uint32_t apat = (uint32_t)((lane & 7) << 4);
    uint32_t aoff[4];
#pragma unroll
    for (int i = 0; i < 4; i++) aoff[i] = (uint32_t)((mw * 64 + i * 16 + arow_l) * 128);

    int brow_l = ((lane >> 4) & 1) * 8 + (lane & 7);
    uint32_t bcolsel = (uint32_t)(((lane >> 3) & 1) * 16);
    uint32_t bpat = (uint32_t)((lane & 7) << 4);
    uint32_t boff[4];
#pragma unroll
    for (int jp = 0; jp < 4; jp++) boff[jp] = (uint32_t)((nw * 64 + jp * 16 + brow_l) * 128);

    uint32_t FULL = sb + BAR_OFF, EMPTY = sb + BAR_OFF + 64;

    for (int kb = 0; kb < nkb; kb++) {
        int s = kb % STAGES;
        mbar_wait(FULL + 8 * s, (kb / STAGES) & 1);
        uint32_t stg = sb + s * STG;
#pragma unroll
        for (int st = 0; st < 4; st++) {          // 4 x K16 per 64-elem block
            uint32_t kbyte = (uint32_t)(st * 32);
            uint32_t axor = (kbyte + acolsel) ^ apat;
            uint32_t bxor = (kbyte + bcolsel) ^ bpat;
            uint32_t ah[4][4];
#pragma unroll
            for (int i = 0; i < 4; i++) {
                uint32_t ad = stg + aoff[i] + axor;
                LDSM_X4(ah[i][0], ah[i][1], ah[i][2], ah[i][3], ad);
            }
            uint32_t bh[2][4];
            {
                uint32_t bd0 = stg + A_BYTES + boff[0] + bxor;
                LDSM_X4(bh[0][0], bh[0][1], bh[0][2], bh[0][3], bd0);
            }
#pragma unroll
            for (int jp = 0; jp < 4; jp++) {
                int cur = jp & 1;
                int nxt = cur ^ 1;
                if (jp < 3) {
                    uint32_t bdn = stg + A_BYTES + boff[jp + 1] + bxor;
                    LDSM_X4(bh[nxt][0], bh[nxt][1], bh[nxt][2], bh[nxt][3], bdn);
                }
#pragma unroll
                for (int i = 0; i < 4; i++) {
                    MMA16816(acc[i][2 * jp],     ah[i], bh[cur][0], bh[cur][1]);
                    MMA16816(acc[i][2 * jp + 1], ah[i], bh[cur][2], bh[cur][3]);
                }
            }
        }
        if (lane == 0) MBAR_ARRIVE(EMPTY + 8 * s);
    }
}

// ----------------------------- GEMM kernels --------------------------------
__global__ __launch_bounds__(160, 2)
void gemm1_tc(const __grid_constant__ CUtensorMap mA,
              const __grid_constant__ CUtensorMap mB,
              const float* __restrict__ bias)
{
    int slot = blockIdx.y;
    if (slot >= g_nslots) return;
    int e = g_slot_e[slot], row0 = g_slot_row0[slot], nv = g_slot_nv[slot];
    int nb = blockIdx.x * BN;

    extern __shared__ __align__(1024) uint8_t smem_buf[];
    uint32_t sb = s2u(smem_buf);
    int tid = threadIdx.x, lane = tid & 31, warp = tid >> 5;

    if (tid == 0) {
        for (int s = 0; s < STAGES; s++) {
            MBAR_INIT(sb + BAR_OFF + 8 * s, 1);
            MBAR_INIT(sb + BAR_OFF + 64 + 8 * s, 4);
        }
    }
    asm volatile("fence.proxy.async.shared::cta;" ::: "memory");
    __syncthreads();

    if (warp == 4) {
        if (lane == 0)
            produce_all(sb, &mA, &mB, row0, e * DF + nb, DM / BKE);
        return;
    }

    float acc[4][8][4];
#pragma unroll
    for (int i = 0; i < 4; i++)
#pragma unroll
        for (int j = 0; j < 8; j++)
#pragma unroll
            for (int q = 0; q < 4; q++) acc[i][j][q] = 0.f;

    int mw = warp & 1, nw = warp >> 1;
    consume_all(sb, DM / BKE, lane, mw, nw, acc);

    int rb = mw * 64 + (lane >> 2);
    int cbase = nb + nw * 64 + 2 * (lane & 3);
    const float* bb = bias + (size_t)e * DF;
#pragma unroll
    for (int i = 0; i < 4; i++) {
#pragma unroll
        for (int half = 0; half < 2; half++) {
            int r = rb + i * 16 + half * 8;
            if (r < nv) {
                size_t rowg = (size_t)(row0 + r);
#pragma unroll
                for (int j = 0; j < 8; j++) {
                    int colg = cbase + j * 8;
                    float2 bv = *(const float2*)(bb + colg);
                    float v0 = fmaxf(acc[i][j][2 * half]     + bv.x, 0.f);
                    float v1 = fmaxf(acc[i][j][2 * half + 1] + bv.y, 0.f);
                    __half2 hp = __floats2half2_rn(v0, v1);
                    *(uint32_t*)(g_Hh + rowg * DF + colg) = *(uint32_t*)&hp;
                }
            }
        }
    }
}

__global__ __launch_bounds__(160, 2)
void gemm2_tc(const __grid_constant__ CUtensorMap mA,
              const __grid_constant__ CUtensorMap mB,
              const float* __restrict__ bias,
              float* __restrict__ out)
{
    int slot = blockIdx.y;
    if (slot >= g_nslots) return;
    int e = g_slot_e[slot], row0 = g_slot_row0[slot], nv = g_slot_nv[slot];
    int nb = blockIdx.x * BN;

    extern __shared__ __align__(1024) uint8_t smem_buf[];
    uint32_t sb = s2u(smem_buf);
    int tid = threadIdx.x, lane = tid & 31, warp = tid >> 5;
    int* toks = (int*)(smem_buf + TOKS_OFF);

    if (tid == 0) {
        for (int s = 0; s < STAGES; s++) {
            MBAR_INIT(sb + BAR_OFF + 8 * s, 1);
            MBAR_INIT(sb + BAR_OFF + 64 + 8 * s, 4);
        }
    }
    if (tid < BM) toks[tid] = g_perm[row0 + min(tid, nv - 1)];
    asm volatile("fence.proxy.async.shared::cta;" ::: "memory");
    __syncthreads();

    if (warp == 4) {
        if (lane == 0)
            produce_all(sb, &mA, &mB, row0, e * DM + nb, DF / BKE);
        return;
    }

    float acc[4][8][4];
#pragma unroll
    for (int i = 0; i < 4; i++)
#pragma unroll
        for (int j = 0; j < 8; j++)
#pragma unroll
            for (int q = 0; q < 4; q++) acc[i][j][q] = 0.f;

    int mw = warp & 1, nw = warp >> 1;
    consume_all(sb, DF / BKE, lane, mw, nw, acc);

    int rb = mw * 64 + (lane >> 2);
    int cbase = nb + nw * 64 + 2 * (lane & 3);
    const float* bb = bias + (size_t)e * DM;
#pragma unroll
    for (int i = 0; i < 4; i++) {
#pragma unroll
        for (int half = 0; half < 2; half++) {
            int r = rb + i * 16 + half * 8;
            if (r < nv) {
                int tok = toks[r];
                float* op = out + (size_t)tok * DM;
#pragma unroll
                for (int j = 0; j < 8; j++) {
                    int colg = cbase + j * 8;
                    float2 bv = *(const float2*)(bb + colg);
                    float2 v;
                    v.x = acc[i][j][2 * half]     + bv.x;
                    v.y = acc[i][j][2 * half + 1] + bv.y;
                    *(float2*)(op + colg) = v;
                }
            }
        }
    }
}

// ------------------------------- host side ---------------------------------
typedef CUresult (CUDAAPI *PFN_encodeTiled)(
    CUtensorMap*, CUtensorMapDataType, cuuint32_t, void*,
    const cuuint64_t*, const cuuint64_t*, const cuuint32_t*, const cuuint32_t*,
    CUtensorMapInterleave, CUtensorMapSwizzle, CUtensorMapL2promotion, CUtensorMapFloatOOBfill);

static PFN_encodeTiled get_encode_fn() {
    static PFN_encodeTiled fn = nullptr;
    if (!fn) {
        void* p = nullptr;
        cudaDriverEntryPointQueryResult st;
#if CUDART_VERSION >= 12050
        cudaGetDriverEntryPointByVersion("cuTensorMapEncodeTiled", &p, 12000, cudaEnableDefault, &st);
#else
        cudaGetDriverEntryPoint("cuTensorMapEncodeTiled", &p, cudaEnableDefault, &st);
#endif
        fn = (PFN_encodeTiled)p;
    }
    return fn;
}

// 2D fp16 map, SW128, box {64, box_rows} (64 fp16 = 128B row = SW128 atom)
static void make_map_2d(CUtensorMap* m, void* ptr, uint64_t d0, uint64_t d1, uint32_t box_rows) {
    cuuint64_t gd[2] = {d0, d1};
    cuuint64_t gs[1] = {d0 * 2};
    cuuint32_t box[2] = {BKE, box_rows};
    cuuint32_t es[2] = {1, 1};
    get_encode_fn()(m, CU_TENSOR_MAP_DATA_TYPE_FLOAT16, 2, ptr, gd, gs, box, es,
                    CU_TENSOR_MAP_INTERLEAVE_NONE, CU_TENSOR_MAP_SWIZZLE_128B,
                    CU_TENSOR_MAP_L2_PROMOTION_L2_128B, CU_TENSOR_MAP_FLOAT_OOB_FILL_NONE);
}

extern "C" void kernel_launch(void* const* d_in, const int* in_sizes, int n_in,
                              void* d_out, int out_size) {
    const float* x  = (const float*)d_in[0];
    const float* sw = (const float*)d_in[1];
    const float* sb = (const float*)d_in[2];
    const float* w1 = (const float*)d_in[3];
    const float* b1 = (const float*)d_in[4];
    const float* w2 = (const float*)d_in[5];
    const float* b2 = (const float*)d_in[6];
    float* out = (float*)d_out;

    void *p_xh, *p_w1h, *p_w2h, *p_hh;
    cudaGetSymbolAddress(&p_xh, g_Xh);
    cudaGetSymbolAddress(&p_w1h, g_w1h);
    cudaGetSymbolAddress(&p_w2h, g_w2h);
    cudaGetSymbolAddress(&p_hh, g_Hh);

    CUtensorMap mXh, mW1h, mW2h, mHh;
    make_map_2d(&mXh,  p_xh,  DM, T_TOK, 128);
    make_map_2d(&mW1h, p_w1h, DM, (uint64_t)NE * DF, 128);
    make_map_2d(&mW2h, p_w2h, DF, (uint64_t)NE * DM, 128);
    make_map_2d(&mHh,  p_hh,  DF, T_TOK, 128);

    cudaFuncSetAttribute(gemm1_tc, cudaFuncAttributeMaxDynamicSharedMemorySize, SMEM_TOTAL);
    cudaFuncSetAttribute(gemm2_tc, cudaFuncAttributeMaxDynamicSharedMemorySize, SMEM_TOTAL);

    {
        int n4 = NE * DF * DM / 4;
        convert_cast_kernel<<<n4 / 256, 256>>>((const float4*)w1, (uint2*)p_w1h, n4);
        convert_cast_kernel<<<n4 / 256, 256>>>((const float4*)w2, (uint2*)p_w2h, n4);
    }

    init_kernel<<<1, 32>>>();
    router_kernel<<<T_TOK / 8, 256>>>(x, sw, sb, out + OFF_PMAX);
    finalize_kernel<<<1, 256>>>(out);
    scatter_gather_kernel<<<T_TOK / 8, 256>>>(x);

    gemm1_tc<<<dim3(DF / BN, 71), 160, SMEM_TOTAL>>>(mXh, mW1h, b1);
    gemm2_tc<<<dim3(DM / BN, 71), 160, SMEM_TOTAL>>>(mHh, mW2h, b2, out);
}